// round 9
// baseline (speedup 1.0000x reference)
#include <cuda_runtime.h>

#define Hh 1024
#define Ww 1024
#define Bb 16
#define DIL 2
#define NTHREADS 256
#define RPB 16                              // rows per block strip
#define BLKS_PER_IMG (Hh / RPB)             // 64
#define NBLOCKS (Bb * BLKS_PER_IMG)         // 1024
#define NELEM ((long long)Bb * Hh * Ww)

#define NEG100_LG2 (-144.269504088896f)     // -100 / ln(2)
#define LN2F (0.6931471805599453f)

__device__ double       g_sum   = 0.0;
__device__ unsigned int g_count = 0u;

// ---------- core math for one output row (4 px) ----------
__device__ __forceinline__ void row_core(const float up[8], const float mid[8],
                                         const float dn[8], float4 t4,
                                         float& uw_acc, float& a_tLp,
                                         float& a_tL1, float& a_L1) {
    float cmn[8], cmx[8];
#pragma unroll
    for (int x = 0; x < 8; ++x) {
        cmn[x] = fminf(up[x], dn[x]);
        cmx[x] = fmaxf(up[x], dn[x]);
    }
    const float tval[4] = { t4.x, t4.y, t4.z, t4.w };
#pragma unroll
    for (int k = 0; k < 4; ++k) {
        const float p = mid[k + 2];
        const float t = tval[k];

        const float mn = fminf(fminf(fminf(cmn[k], mid[k]),
                                     fminf(cmn[k + 4], mid[k + 4])),
                               cmn[k + 2]);
        const float mx = fmaxf(fmaxf(fmaxf(cmx[k], mid[k]),
                                     fmaxf(cmx[k + 4], mid[k + 4])),
                               cmx[k + 2]);
        const float uw = fmaxf(p - mn, mx - p);     // == max_nb |p - nb|

        if (p >= 0.5f)                              // thred: predicated FFMA
            uw_acc = fmaf(uw, p, uw_acc);

        const float Lp = fmaxf(__log2f(p),        NEG100_LG2);
        const float L1 = fmaxf(__log2f(1.0f - p), NEG100_LG2);
        a_tLp = fmaf(t, Lp, a_tLp);
        a_tL1 = fmaf(t, L1, a_tL1);
        a_L1 += L1;
    }
}

// ---------- interior loader: 3 unconditional LDG.128 + mask-FMUL halo fixup ----------
__device__ __forceinline__ void load_win_i(float w[8], const float* __restrict__ r,
                                           int offL, int x4, int offR,
                                           float mL, float mR) {
    const float4 L = *reinterpret_cast<const float4*>(r + offL);
    const float4 C = *reinterpret_cast<const float4*>(r + x4);
    const float4 R = *reinterpret_cast<const float4*>(r + offR);
    w[0] = L.z * mL; w[1] = L.w * mL;
    w[2] = C.x; w[3] = C.y; w[4] = C.z; w[5] = C.w;
    w[6] = R.x * mR; w[7] = R.y * mR;
}

// ---------- edge loader: predicated, zero pad outside image ----------
__device__ __forceinline__ void load_win_e(float w[8], const float* __restrict__ img,
                                           int gy, int x4, bool leftEdge, bool rightEdge) {
    float4 L = make_float4(0.f, 0.f, 0.f, 0.f);
    float4 C = L, R = L;
    if (gy >= 0 && gy < Hh) {
        const float* r = img + (size_t)gy * Ww;
        if (!leftEdge)  L = *reinterpret_cast<const float4*>(r + x4 - 4);
        C = *reinterpret_cast<const float4*>(r + x4);
        if (!rightEdge) R = *reinterpret_cast<const float4*>(r + x4 + 4);
    }
    w[0] = L.z; w[1] = L.w;
    w[2] = C.x; w[3] = C.y; w[4] = C.z; w[5] = C.w;
    w[6] = R.x; w[7] = R.y;
}

__global__ __launch_bounds__(NTHREADS, 3)
void consistency_main(const float* __restrict__ yt, const float* __restrict__ yp,
                      float* __restrict__ out) {
    __shared__ float warp_sums[NTHREADS / 32];

    const int blk = blockIdx.x;                     // 0..1023
    const int b   = blk >> 6;                       // image
    const int yg  = (blk & (BLKS_PER_IMG - 1)) * RPB;
    const int tid = threadIdx.x;
    const int x4  = tid * 4;
    const bool leftEdge  = (tid == 0);
    const bool rightEdge = (tid == NTHREADS - 1);

    const float* img  = yp + (size_t)b * Hh * Ww;
    const float* timg = yt + (size_t)b * Hh * Ww;

    float uw_acc = 0.f, a_tLp = 0.f, a_tL1 = 0.f, a_L1 = 0.f;

    if (yg != 0 && yg != Hh - RPB) {
        // ---------- interior strips: no vertical-boundary predication ----------
        const int offL = leftEdge  ? x4 : x4 - 4;   // clamped; halo zeroed by mask
        const int offR = rightEdge ? x4 : x4 + 4;
        const float mL = leftEdge  ? 0.f : 1.f;
        const float mR = rightEdge ? 0.f : 1.f;
        const float* base = img + (size_t)yg * Ww;  // row yg; offsets are constants

#pragma unroll 1
        for (int c = 0; c < 2; ++c) {
            float w0[8], w1[8], w2[8], w3[8];
            load_win_i(w0, base + (c - 2) * Ww, offL, x4, offR, mL, mR);
            load_win_i(w1, base + c * Ww,       offL, x4, offR, mL, mR);

#pragma unroll
            for (int j = c; j < RPB; j += 4) {
                load_win_i(w2, base + (j + 2) * Ww, offL, x4, offR, mL, mR);
                load_win_i(w3, base + (j + 4) * Ww, offL, x4, offR, mL, mR);
                const float4 tA = *reinterpret_cast<const float4*>(
                    timg + (size_t)(yg + j) * Ww + x4);
                const float4 tB = *reinterpret_cast<const float4*>(
                    timg + (size_t)(yg + j + 2) * Ww + x4);

                row_core(w0, w1, w2, tA, uw_acc, a_tLp, a_tL1, a_L1);  // row j
                row_core(w1, w2, w3, tB, uw_acc, a_tLp, a_tL1, a_L1);  // row j+2

#pragma unroll
                for (int q = 0; q < 8; ++q) { w0[q] = w2[q]; w1[q] = w3[q]; }
            }
        }
    } else {
        // ---------- top/bottom strips (2/64): predicated loads, small code ----------
#pragma unroll 1
        for (int c = 0; c < 2; ++c) {
            float w0[8], w1[8], w2[8], w3[8];
            load_win_e(w0, img, yg + c - 2, x4, leftEdge, rightEdge);
            load_win_e(w1, img, yg + c,     x4, leftEdge, rightEdge);

#pragma unroll 1
            for (int j = c; j < RPB; j += 4) {
                load_win_e(w2, img, yg + j + 2, x4, leftEdge, rightEdge);
                load_win_e(w3, img, yg + j + 4, x4, leftEdge, rightEdge);
                const float4 tA = *reinterpret_cast<const float4*>(
                    timg + (size_t)(yg + j) * Ww + x4);
                const float4 tB = *reinterpret_cast<const float4*>(
                    timg + (size_t)(yg + j + 2) * Ww + x4);

                row_core(w0, w1, w2, tA, uw_acc, a_tLp, a_tL1, a_L1);
                row_core(w1, w2, w3, tB, uw_acc, a_tLp, a_tL1, a_L1);

#pragma unroll
                for (int q = 0; q < 8; ++q) { w0[q] = w2[q]; w1[q] = w3[q]; }
            }
        }
    }

    // bce_sum(lg2) = -(Σ t·Lp + Σ L1 - Σ t·L1); fold ln2 once.
    float lsum = fmaf(LN2F, a_tL1 - a_tLp - a_L1, uw_acc);

    // Block reduction
#pragma unroll
    for (int off = 16; off > 0; off >>= 1)
        lsum += __shfl_xor_sync(0xFFFFFFFFu, lsum, off);
    if ((tid & 31) == 0) warp_sums[tid >> 5] = lsum;
    __syncthreads();
    if (tid == 0) {
        float v = 0.f;
#pragma unroll
        for (int w = 0; w < NTHREADS / 32; ++w) v += warp_sums[w];

        // Fused final reduction: last-arriving block writes the mean.
        atomicAdd(&g_sum, (double)v);
        __threadfence();
        const unsigned int old = atomicAdd(&g_count, 1u);
        if (old == NBLOCKS - 1) {
            const double total = atomicAdd(&g_sum, 0.0);   // coherent read
            out[0] = (float)(total / (double)NELEM);
            g_sum   = 0.0;                                  // reset for next replay
            __threadfence();
            g_count = 0u;
        }
    }
}

extern "C" void kernel_launch(void* const* d_in, const int* in_sizes, int n_in,
                              void* d_out, int out_size) {
    const float* y_true = (const float*)d_in[0];
    const float* y_pred = (const float*)d_in[1];
    float* out = (float*)d_out;
    consistency_main<<<NBLOCKS, NTHREADS>>>(y_true, y_pred, out);
}

// round 10
// speedup vs baseline: 1.0288x; 1.0288x over previous
#include <cuda_runtime.h>

#define Hh 1024
#define Ww 1024
#define Bb 16
#define DIL 2
#define NTHREADS 256
#define RPB 8                               // rows per block strip
#define BLKS_PER_IMG (Hh / RPB)             // 128
#define NBLOCKS (Bb * BLKS_PER_IMG)         // 2048
#define NELEM ((long long)Bb * Hh * Ww)

#define NEG100_LG2 (-144.269504088896f)     // -100 / ln(2)
#define LN2F (0.6931471805599453f)

__device__ double       g_sum   = 0.0;
__device__ unsigned int g_count = 0u;

// Assemble the 8-wide window data[x4-2 .. x4+5] for row gy from three aligned
// float4 global loads, zero-padded at image borders.
__device__ __forceinline__ void load_winG(float w[8], const float* __restrict__ img,
                                          int gy, int x4, bool leftEdge, bool rightEdge) {
    float4 L = make_float4(0.f, 0.f, 0.f, 0.f);
    float4 C = L, R = L;
    if (gy >= 0 && gy < Hh) {                       // uniform across the warp
        const float* r = img + (size_t)gy * Ww;
        if (!leftEdge)  L = *reinterpret_cast<const float4*>(r + x4 - 4);
        C = *reinterpret_cast<const float4*>(r + x4);
        if (!rightEdge) R = *reinterpret_cast<const float4*>(r + x4 + 4);
    }
    w[0] = L.z; w[1] = L.w;
    w[2] = C.x; w[3] = C.y; w[4] = C.z; w[5] = C.w;
    w[6] = R.x; w[7] = R.y;
}

// One output row (4 px). Accumulators:
//   uw_acc += max_nb|p-nb| * thred ; lg2-domain BCE split into 3 FMA accumulators.
__device__ __forceinline__ void row_loss(const float up[8], const float mid[8],
                                         const float dn[8], float4 t4,
                                         float& uw_acc, float& a_tLp,
                                         float& a_tL1, float& a_L1) {
    float cmn[8], cmx[8];
#pragma unroll
    for (int x = 0; x < 8; ++x) {
        cmn[x] = fminf(up[x], dn[x]);
        cmx[x] = fmaxf(up[x], dn[x]);
    }
    const float tval[4] = { t4.x, t4.y, t4.z, t4.w };
#pragma unroll
    for (int k = 0; k < 4; ++k) {
        const float p = mid[k + 2];
        const float t = tval[k];

        const float mn = fminf(fminf(fminf(cmn[k], mid[k]),
                                     fminf(cmn[k + 4], mid[k + 4])),
                               cmn[k + 2]);
        const float mx = fmaxf(fmaxf(fmaxf(cmx[k], mid[k]),
                                     fmaxf(cmx[k + 4], mid[k + 4])),
                               cmx[k + 2]);
        const float uw = fmaxf(p - mn, mx - p);     // == max_nb |p - nb|

        if (p >= 0.5f)                              // thred: predicated FFMA
            uw_acc = fmaf(uw, p, uw_acc);

        const float Lp = fmaxf(__log2f(p),        NEG100_LG2);
        const float L1 = fmaxf(__log2f(1.0f - p), NEG100_LG2);
        a_tLp = fmaf(t, Lp, a_tLp);
        a_tL1 = fmaf(t, L1, a_tL1);
        a_L1 += L1;
    }
}

__global__ __launch_bounds__(NTHREADS, 3)
void consistency_main(const float* __restrict__ yt, const float* __restrict__ yp,
                      float* __restrict__ out) {
    __shared__ float warp_sums[NTHREADS / 32];

    const int blk = blockIdx.x;                     // 0..2047
    const int b   = blk >> 7;                       // image
    const int yg  = (blk & (BLKS_PER_IMG - 1)) * RPB;
    const int tid = threadIdx.x;
    const int x4  = tid * 4;
    const bool leftEdge  = (tid == 0);
    const bool rightEdge = (tid == NTHREADS - 1);

    const float* img  = yp + (size_t)b * Hh * Ww;
    const float* timg = yt + (size_t)b * Hh * Ww;

    float uw_acc = 0.f, a_tLp = 0.f, a_tL1 = 0.f, a_L1 = 0.f;

    // Two parity chains; fully unrolled (2 double-steps per chain) so rolling
    // copies become register renames and bodies overlap for ILP.
#pragma unroll 1
    for (int c = 0; c < 2; ++c) {
        float w0[8], w1[8], w2[8], w3[8];
        load_winG(w0, img, yg + c - 2, x4, leftEdge, rightEdge);
        load_winG(w1, img, yg + c,     x4, leftEdge, rightEdge);

#pragma unroll
        for (int j = c; j < RPB; j += 4) {
            load_winG(w2, img, yg + j + 2, x4, leftEdge, rightEdge);
            load_winG(w3, img, yg + j + 4, x4, leftEdge, rightEdge);
            const float4 tA = *reinterpret_cast<const float4*>(
                timg + (size_t)(yg + j) * Ww + x4);
            const float4 tB = *reinterpret_cast<const float4*>(
                timg + (size_t)(yg + j + 2) * Ww + x4);

            row_loss(w0, w1, w2, tA, uw_acc, a_tLp, a_tL1, a_L1);   // row j
            row_loss(w1, w2, w3, tB, uw_acc, a_tLp, a_tL1, a_L1);   // row j+2

#pragma unroll
            for (int q = 0; q < 8; ++q) { w0[q] = w2[q]; w1[q] = w3[q]; }
        }
    }

    // bce_sum(lg2) = -(Σ t·Lp + Σ L1 - Σ t·L1); fold ln2 once.
    float lsum = fmaf(LN2F, a_tL1 - a_tLp - a_L1, uw_acc);

    // Block reduction
#pragma unroll
    for (int off = 16; off > 0; off >>= 1)
        lsum += __shfl_xor_sync(0xFFFFFFFFu, lsum, off);
    if ((tid & 31) == 0) warp_sums[tid >> 5] = lsum;
    __syncthreads();
    if (tid == 0) {
        float v = 0.f;
#pragma unroll
        for (int w = 0; w < NTHREADS / 32; ++w) v += warp_sums[w];

        // Fused final reduction: last-arriving block writes the mean.
        atomicAdd(&g_sum, (double)v);
        __threadfence();
        const unsigned int old = atomicAdd(&g_count, 1u);
        if (old == NBLOCKS - 1) {
            const double total = atomicAdd(&g_sum, 0.0);   // coherent read
            out[0] = (float)(total / (double)NELEM);
            g_sum   = 0.0;                                  // reset for next replay
            __threadfence();
            g_count = 0u;
        }
    }
}

extern "C" void kernel_launch(void* const* d_in, const int* in_sizes, int n_in,
                              void* d_out, int out_size) {
    const float* y_true = (const float*)d_in[0];
    const float* y_pred = (const float*)d_in[1];
    float* out = (float*)d_out;
    consistency_main<<<NBLOCKS, NTHREADS>>>(y_true, y_pred, out);
}

// round 11
// speedup vs baseline: 1.1031x; 1.0723x over previous
#include <cuda_runtime.h>

#define Hh 1024
#define Ww 1024
#define Bb 16
#define DIL 2
#define NTHREADS 256
#define RPB 16                              // rows per block strip
#define BLKS_PER_IMG (Hh / RPB)             // 64
#define NBLOCKS (Bb * BLKS_PER_IMG)         // 1024
#define NELEM ((long long)Bb * Hh * Ww)

#define NEG100_LG2 (-144.269504088896f)     // -100 / ln(2)
#define LN2F (0.6931471805599453f)

__device__ double       g_sum   = 0.0;
__device__ unsigned int g_count = 0u;

// Per-row separable state: horizontal 3-point (dilated) min/max INCLUDING the
// center, plus the 4 center pixels. Including the center is valid because
// uw = max(p - mn, mx - p) >= 0, so min(mn_nb, p)/max(mx_nb, p) leave it unchanged.
struct RowS {
    float mn[4], mx[4], cen[4];
};

__device__ __forceinline__ void load_row(RowS& s, const float* __restrict__ img,
                                         int gy, int x4, bool leftEdge, bool rightEdge) {
    float4 L = make_float4(0.f, 0.f, 0.f, 0.f);
    float4 C = L, R = L;
    if (gy >= 0 && gy < Hh) {                       // uniform across the warp
        const float* r = img + (size_t)gy * Ww;
        if (!leftEdge)  L = *reinterpret_cast<const float4*>(r + x4 - 4);
        C = *reinterpret_cast<const float4*>(r + x4);
        if (!rightEdge) R = *reinterpret_cast<const float4*>(r + x4 + 4);
    }
    // window w = {L.z, L.w, C.x, C.y, C.z, C.w, R.x, R.y}; h-reduce (w[k],w[k+2],w[k+4])
    s.mn[0] = fminf(fminf(L.z, C.x), C.z);
    s.mn[1] = fminf(fminf(L.w, C.y), C.w);
    s.mn[2] = fminf(fminf(C.x, C.z), R.x);
    s.mn[3] = fminf(fminf(C.y, C.w), R.y);
    s.mx[0] = fmaxf(fmaxf(L.z, C.x), C.z);
    s.mx[1] = fmaxf(fmaxf(L.w, C.y), C.w);
    s.mx[2] = fmaxf(fmaxf(C.x, C.z), R.x);
    s.mx[3] = fmaxf(fmaxf(C.y, C.w), R.y);
    s.cen[0] = C.x; s.cen[1] = C.y; s.cen[2] = C.z; s.cen[3] = C.w;
}

// One output row (4 px) from rows (up, mid, dn).
__device__ __forceinline__ void row_loss(const RowS& up, const RowS& mid, const RowS& dn,
                                         float4 t4,
                                         float& uw_acc, float& a_tLp,
                                         float& a_tL1, float& a_L1) {
    const float tval[4] = { t4.x, t4.y, t4.z, t4.w };
#pragma unroll
    for (int k = 0; k < 4; ++k) {
        const float p = mid.cen[k];
        const float t = tval[k];

        const float mn = fminf(fminf(up.mn[k], dn.mn[k]), mid.mn[k]);
        const float mx = fmaxf(fmaxf(up.mx[k], dn.mx[k]), mid.mx[k]);
        const float uw = fmaxf(p - mn, mx - p);     // == max_nb |p - nb|

        if (p >= 0.5f)                              // thred: predicated FFMA
            uw_acc = fmaf(uw, p, uw_acc);

        const float Lp = fmaxf(__log2f(p),        NEG100_LG2);
        const float L1 = fmaxf(__log2f(1.0f - p), NEG100_LG2);
        a_tLp = fmaf(t, Lp, a_tLp);
        a_tL1 = fmaf(t, L1, a_tL1);
        a_L1 += L1;
    }
}

__global__ __launch_bounds__(NTHREADS, 3)
void consistency_main(const float* __restrict__ yt, const float* __restrict__ yp,
                      float* __restrict__ out) {
    __shared__ float warp_sums[NTHREADS / 32];

    const int blk = blockIdx.x;                     // 0..1023
    const int b   = blk >> 6;                       // image
    const int yg  = (blk & (BLKS_PER_IMG - 1)) * RPB;
    const int tid = threadIdx.x;
    const int x4  = tid * 4;
    const bool leftEdge  = (tid == 0);
    const bool rightEdge = (tid == NTHREADS - 1);

    const float* img  = yp + (size_t)b * Hh * Ww;
    const float* timg = yt + (size_t)b * Hh * Ww;

    float uw_acc = 0.f, a_tLp = 0.f, a_tL1 = 0.f, a_L1 = 0.f;

    // Two parity chains (vertical neighbors are +-2). Each loaded row is
    // h-reduced ONCE and reused as up/mid/dn; chain fully unrolled so the
    // rolling copies become register renames.
#pragma unroll 1
    for (int c = 0; c < 2; ++c) {
        RowS s0, s1, s2, s3;
        load_row(s0, img, yg + c - 2, x4, leftEdge, rightEdge);
        load_row(s1, img, yg + c,     x4, leftEdge, rightEdge);

#pragma unroll
        for (int j = c; j < RPB; j += 4) {
            load_row(s2, img, yg + j + 2, x4, leftEdge, rightEdge);
            load_row(s3, img, yg + j + 4, x4, leftEdge, rightEdge);
            const float4 tA = *reinterpret_cast<const float4*>(
                timg + (size_t)(yg + j) * Ww + x4);
            const float4 tB = *reinterpret_cast<const float4*>(
                timg + (size_t)(yg + j + 2) * Ww + x4);

            row_loss(s0, s1, s2, tA, uw_acc, a_tLp, a_tL1, a_L1);   // row j
            row_loss(s1, s2, s3, tB, uw_acc, a_tLp, a_tL1, a_L1);   // row j+2

            s0 = s2; s1 = s3;                       // renames under full unroll
        }
    }

    // bce_sum(lg2) = -(Σ t·Lp + Σ L1 - Σ t·L1); fold ln2 once.
    float lsum = fmaf(LN2F, a_tL1 - a_tLp - a_L1, uw_acc);

    // Block reduction
#pragma unroll
    for (int off = 16; off > 0; off >>= 1)
        lsum += __shfl_xor_sync(0xFFFFFFFFu, lsum, off);
    if ((tid & 31) == 0) warp_sums[tid >> 5] = lsum;
    __syncthreads();
    if (tid == 0) {
        float v = 0.f;
#pragma unroll
        for (int w = 0; w < NTHREADS / 32; ++w) v += warp_sums[w];

        // Fused final reduction: last-arriving block writes the mean.
        atomicAdd(&g_sum, (double)v);
        __threadfence();
        const unsigned int old = atomicAdd(&g_count, 1u);
        if (old == NBLOCKS - 1) {
            const double total = atomicAdd(&g_sum, 0.0);   // coherent read
            out[0] = (float)(total / (double)NELEM);
            g_sum   = 0.0;                                  // reset for next replay
            __threadfence();
            g_count = 0u;
        }
    }
}

extern "C" void kernel_launch(void* const* d_in, const int* in_sizes, int n_in,
                              void* d_out, int out_size) {
    const float* y_true = (const float*)d_in[0];
    const float* y_pred = (const float*)d_in[1];
    float* out = (float*)d_out;
    consistency_main<<<NBLOCKS, NTHREADS>>>(y_true, y_pred, out);
}

// round 12
// speedup vs baseline: 1.1744x; 1.0646x over previous
#include <cuda_runtime.h>

#define Hh 1024
#define Ww 1024
#define Bb 16
#define DIL 2
#define NTHREADS 256
#define RPB 16                              // rows per block strip
#define BLKS_PER_IMG (Hh / RPB)             // 64
#define NBLOCKS (Bb * BLKS_PER_IMG)         // 1024
#define NELEM ((long long)Bb * Hh * Ww)

#define NEG100_LG2 (-144.269504088896f)     // -100 / ln(2)
#define LN2F (0.6931471805599453f)

__device__ double       g_sum   = 0.0;
__device__ unsigned int g_count = 0u;

// Per-row separable state: horizontal 3-point (dilated) min/max INCLUDING the
// center (valid: uw = max(p-mn, mx-p) >= 0 so including p changes nothing),
// plus the 4 center pixels.
struct RowS {
    float mn[4], mx[4], cen[4];
};

__device__ __forceinline__ void load_row(RowS& s, const float* __restrict__ img,
                                         int gy, int x4, bool leftEdge, bool rightEdge) {
    float4 L = make_float4(0.f, 0.f, 0.f, 0.f);
    float4 C = L, R = L;
    if (gy >= 0 && gy < Hh) {                       // uniform across the warp
        const float* r = img + (size_t)gy * Ww;
        if (!leftEdge)  L = *reinterpret_cast<const float4*>(r + x4 - 4);
        C = *reinterpret_cast<const float4*>(r + x4);
        if (!rightEdge) R = *reinterpret_cast<const float4*>(r + x4 + 4);
    }
    // window w = {L.z, L.w, C.x, C.y, C.z, C.w, R.x, R.y}; h-reduce (w[k],w[k+2],w[k+4])
    s.mn[0] = fminf(fminf(L.z, C.x), C.z);
    s.mn[1] = fminf(fminf(L.w, C.y), C.w);
    s.mn[2] = fminf(fminf(C.x, C.z), R.x);
    s.mn[3] = fminf(fminf(C.y, C.w), R.y);
    s.mx[0] = fmaxf(fmaxf(L.z, C.x), C.z);
    s.mx[1] = fmaxf(fmaxf(L.w, C.y), C.w);
    s.mx[2] = fmaxf(fmaxf(C.x, C.z), R.x);
    s.mx[3] = fmaxf(fmaxf(C.y, C.w), R.y);
    s.cen[0] = C.x; s.cen[1] = C.y; s.cen[2] = C.z; s.cen[3] = C.w;
}

// One output row (4 px) from rows (up, mid, dn).
__device__ __forceinline__ void row_loss(const RowS& up, const RowS& mid, const RowS& dn,
                                         float4 t4,
                                         float& uw_acc, float& a_tLp,
                                         float& a_tL1, float& a_L1) {
    const float tval[4] = { t4.x, t4.y, t4.z, t4.w };
#pragma unroll
    for (int k = 0; k < 4; ++k) {
        const float p = mid.cen[k];
        const float t = tval[k];

        const float mn = fminf(fminf(up.mn[k], dn.mn[k]), mid.mn[k]);
        const float mx = fmaxf(fmaxf(up.mx[k], dn.mx[k]), mid.mx[k]);
        const float uw = fmaxf(p - mn, mx - p);     // == max_nb |p - nb|

        if (p >= 0.5f)                              // thred: predicated FFMA
            uw_acc = fmaf(uw, p, uw_acc);

        // Lp needs the -100 clamp (p can be exactly 0 -> log = -inf).
        // L1 does NOT: fp32 p < 1 gives 1-p >= 5.96e-8, log2 >= -24 > -144.27.
        const float Lp = fmaxf(__log2f(p), NEG100_LG2);
        const float L1 = __log2f(1.0f - p);
        a_tLp = fmaf(t, Lp, a_tLp);
        a_tL1 = fmaf(t, L1, a_tL1);
        a_L1 += L1;
    }
}

__global__ __launch_bounds__(NTHREADS, 4)
void consistency_main(const float* __restrict__ yt, const float* __restrict__ yp,
                      float* __restrict__ out) {
    __shared__ float warp_sums[NTHREADS / 32];

    const int blk = blockIdx.x;                     // 0..1023
    const int b   = blk >> 6;                       // image
    const int yg  = (blk & (BLKS_PER_IMG - 1)) * RPB;
    const int tid = threadIdx.x;
    const int x4  = tid * 4;
    const bool leftEdge  = (tid == 0);
    const bool rightEdge = (tid == NTHREADS - 1);

    const float* img  = yp + (size_t)b * Hh * Ww;
    const float* timg = yt + (size_t)b * Hh * Ww;

    float uw_acc = 0.f, a_tLp = 0.f, a_tL1 = 0.f, a_L1 = 0.f;

    // Two parity chains (vertical neighbors are +-2). Single-row steps keep
    // live state to 3 RowS (fits the 64-reg budget for 4 blocks/SM); the chain
    // is fully unrolled so the rotation is register renaming.
#pragma unroll 1
    for (int c = 0; c < 2; ++c) {
        RowS r0, r1, r2;
        load_row(r0, img, yg + c - 2, x4, leftEdge, rightEdge);
        load_row(r1, img, yg + c,     x4, leftEdge, rightEdge);

#pragma unroll
        for (int j = c; j < RPB; j += 2) {
            load_row(r2, img, yg + j + 2, x4, leftEdge, rightEdge);
            const float4 t4 = *reinterpret_cast<const float4*>(
                timg + (size_t)(yg + j) * Ww + x4);

            row_loss(r0, r1, r2, t4, uw_acc, a_tLp, a_tL1, a_L1);   // row j

            r0 = r1; r1 = r2;                       // renames under full unroll
        }
    }

    // bce_sum(lg2) = -(Σ t·Lp + Σ L1 - Σ t·L1); fold ln2 once.
    float lsum = fmaf(LN2F, a_tL1 - a_tLp - a_L1, uw_acc);

    // Block reduction
#pragma unroll
    for (int off = 16; off > 0; off >>= 1)
        lsum += __shfl_xor_sync(0xFFFFFFFFu, lsum, off);
    if ((tid & 31) == 0) warp_sums[tid >> 5] = lsum;
    __syncthreads();
    if (tid == 0) {
        float v = 0.f;
#pragma unroll
        for (int w = 0; w < NTHREADS / 32; ++w) v += warp_sums[w];

        // Fused final reduction: last-arriving block writes the mean.
        atomicAdd(&g_sum, (double)v);
        __threadfence();
        const unsigned int old = atomicAdd(&g_count, 1u);
        if (old == NBLOCKS - 1) {
            const double total = atomicAdd(&g_sum, 0.0);   // coherent read
            out[0] = (float)(total / (double)NELEM);
            g_sum   = 0.0;                                  // reset for next replay
            __threadfence();
            g_count = 0u;
        }
    }
}

extern "C" void kernel_launch(void* const* d_in, const int* in_sizes, int n_in,
                              void* d_out, int out_size) {
    const float* y_true = (const float*)d_in[0];
    const float* y_pred = (const float*)d_in[1];
    float* out = (float*)d_out;
    consistency_main<<<NBLOCKS, NTHREADS>>>(y_true, y_pred, out);
}